// round 15
// baseline (speedup 1.0000x reference)
#include <cuda_runtime.h>
#include <cuda_bf16.h>
#include <math.h>
#include <stdint.h>

// ---------------- problem constants ----------------
#define N_TOK   4096
#define DMODEL  1024
#define NEXP    8
#define HID     1024
#define TOPK    2

// GEMM tiling (mma.sync bf16 path)
#define BM 128
#define BN 64
#define BK 32
#define APAD 8
#define BPAD 8
#define ASTR (BK + APAD)
#define BSTR (BN + BPAD)

#define MAX_MBLOCKS 104
#define MAX_ROWS    (MAX_MBLOCKS * BM)   // 13312

// dynamic smem layouts
#define S1_AH_B   (BM * ASTR * 2)                 // 10240
#define S1_B_B    (4 * BK * BSTR * 2)             // 18432
#define S1_STAGE  (2 * S1_AH_B + S1_B_B)          // 38912
#define S1_TOTAL  (512 + 2 * S1_STAGE)            // 78336  (2-stage, 2 CTAs/SM)

#define S2_B_B    (2 * BK * BSTR * 2)             // 9216
#define S2_STAGE  (2 * S1_AH_B + S2_B_B)          // 29696
#define S2_TOTAL  (3 * S2_STAGE)                  // 89088  (3-stage, 2 CTAs/SM)

// ---------------- device scratch ----------------
__device__ int   g_counts[NEXP];
__device__ float g_probs[N_TOK * NEXP];
__device__ float g_lse2[N_TOK];
__device__ float g_probs_sum[NEXP];
__device__ float g_zsum;
__device__ int   g_expert_idx[N_TOK * TOPK];
__device__ float g_gate_w[N_TOK * TOPK];
__device__ int   g_row_tok[MAX_ROWS];
__device__ float g_row_w[MAX_ROWS];
__device__ int   g_row_pos[N_TOK * TOPK];
__device__ int   g_seg_start[NEXP + 1];
__device__ int   g_mb_expert[MAX_MBLOCKS];
__device__ int   g_n_mblocks;

__device__ __nv_bfloat16 g_x_hi[(size_t)N_TOK * DMODEL];
__device__ __nv_bfloat16 g_x_lo[(size_t)N_TOK * DMODEL];
__device__ __nv_bfloat16 g_w1_hi[(size_t)(NEXP + 1) * DMODEL * HID];
__device__ __nv_bfloat16 g_w1_lo[(size_t)(NEXP + 1) * DMODEL * HID];
__device__ __nv_bfloat16 g_w3_hi[(size_t)(NEXP + 1) * DMODEL * HID];
__device__ __nv_bfloat16 g_w3_lo[(size_t)(NEXP + 1) * DMODEL * HID];
__device__ __nv_bfloat16 g_w2_hi[(size_t)(NEXP + 1) * HID * DMODEL];
__device__ __nv_bfloat16 g_w2_lo[(size_t)(NEXP + 1) * HID * DMODEL];
__device__ __nv_bfloat16 g_h_hi[(size_t)MAX_ROWS * HID];
__device__ __nv_bfloat16 g_h_lo[(size_t)MAX_ROWS * HID];
__device__ float         g_ro[(size_t)MAX_ROWS * DMODEL];

// ---------------- asm helpers ----------------
__device__ __forceinline__ uint32_t smaddr(const void* p) {
    return (uint32_t)__cvta_generic_to_shared(p);
}
__device__ __forceinline__ void cpa16(uint32_t dst, const void* src, int szbytes) {
    asm volatile("cp.async.cg.shared.global [%0],[%1],16,%2;"
                 :: "r"(dst), "l"(src), "r"(szbytes));
}
__device__ __forceinline__ void cpa_commit() { asm volatile("cp.async.commit_group;"); }
template <int N>
__device__ __forceinline__ void cpa_wait() { asm volatile("cp.async.wait_group %0;" :: "n"(N)); }
__device__ __forceinline__ void ldsm4(uint32_t& r0, uint32_t& r1, uint32_t& r2, uint32_t& r3, uint32_t a) {
    asm volatile("ldmatrix.sync.aligned.m8n8.x4.shared.b16 {%0,%1,%2,%3},[%4];"
                 : "=r"(r0), "=r"(r1), "=r"(r2), "=r"(r3) : "r"(a));
}
__device__ __forceinline__ void ldsm4t(uint32_t& r0, uint32_t& r1, uint32_t& r2, uint32_t& r3, uint32_t a) {
    asm volatile("ldmatrix.sync.aligned.m8n8.x4.trans.shared.b16 {%0,%1,%2,%3},[%4];"
                 : "=r"(r0), "=r"(r1), "=r"(r2), "=r"(r3) : "r"(a));
}
__device__ __forceinline__ void mma16816(float* c, const uint32_t* a, uint32_t b0, uint32_t b1) {
    asm volatile("mma.sync.aligned.m16n8k16.row.col.f32.bf16.bf16.f32 "
                 "{%0,%1,%2,%3},{%4,%5,%6,%7},{%8,%9},{%0,%1,%2,%3};"
                 : "+f"(c[0]), "+f"(c[1]), "+f"(c[2]), "+f"(c[3])
                 : "r"(a[0]), "r"(a[1]), "r"(a[2]), "r"(a[3]), "r"(b0), "r"(b1));
}

// ---------------- split 8 fp32 -> 16B hi + 16B lo ----------------
__device__ __forceinline__ void split8v(const float4 a, const float4 b,
                                        __nv_bfloat16* __restrict__ hi,
                                        __nv_bfloat16* __restrict__ lo, size_t off) {
    float f[8] = { a.x, a.y, a.z, a.w, b.x, b.y, b.z, b.w };
    uint32_t ph[4], pl[4];
#pragma unroll
    for (int i = 0; i < 4; i++) {
        __nv_bfloat16 h0 = __float2bfloat16(f[2 * i]);
        __nv_bfloat16 h1 = __float2bfloat16(f[2 * i + 1]);
        __nv_bfloat162 hv(h0, h1);
        ph[i] = *(uint32_t*)&hv;
        __nv_bfloat162 lv(__float2bfloat16(f[2 * i] - __bfloat162float(h0)),
                          __float2bfloat16(f[2 * i + 1] - __bfloat162float(h1)));
        pl[i] = *(uint32_t*)&lv;
    }
    *(uint4*)(hi + off) = make_uint4(ph[0], ph[1], ph[2], ph[3]);
    *(uint4*)(lo + off) = make_uint4(pl[0], pl[1], pl[2], pl[3]);
}

// 16 elems per thread, 4 independent 16B loads up front (MLP=4)
__device__ __forceinline__ void split16(const float* __restrict__ src,
                                        __nv_bfloat16* __restrict__ hi,
                                        __nv_bfloat16* __restrict__ lo, size_t off) {
    float4 v0 = *(const float4*)(src + off);
    float4 v1 = *(const float4*)(src + off + 4);
    float4 v2 = *(const float4*)(src + off + 8);
    float4 v3 = *(const float4*)(src + off + 12);
    split8v(v0, v1, hi, lo, off);
    split8v(v2, v3, hi, lo, off + 8);
}

// ---------------- prep: x split + init ----------------
__global__ __launch_bounds__(256) void prep_kernel(const float* __restrict__ x) {
    int gid = blockIdx.x * blockDim.x + threadIdx.x;
    size_t off = (size_t)gid * 16;
    if (off < (size_t)N_TOK * DMODEL) split16(x, g_x_hi, g_x_lo, off);
    if (gid < MAX_ROWS) g_row_tok[gid] = -1;
    if (gid < NEXP) g_counts[gid] = 0;
    if (gid == 0) g_zsum = 0.0f;
}

// ---------------- w1/w3 splits (gate stage1) ----------------
// regions (1M units): w1[0,8) sw1[8,9) w3[9,17) sw3[17,18)
__global__ __launch_bounds__(256) void splitw13_kernel(const float* __restrict__ w1,
                                                       const float* __restrict__ w3,
                                                       const float* __restrict__ sw1,
                                                       const float* __restrict__ sw3) {
    const size_t M1 = (size_t)DMODEL * HID;
    const size_t EW = (size_t)NEXP * M1;
    size_t off = ((size_t)blockIdx.x * blockDim.x + threadIdx.x) * 16;
    if (off < EW)  { split16(w1,  g_w1_hi,      g_w1_lo,      off); return; }
    off -= EW;
    if (off < M1)  { split16(sw1, g_w1_hi + EW, g_w1_lo + EW, off); return; }
    off -= M1;
    if (off < EW)  { split16(w3,  g_w3_hi,      g_w3_lo,      off); return; }
    off -= EW;
    if (off < M1)  { split16(sw3, g_w3_hi + EW, g_w3_lo + EW, off); return; }
}

// ---------------- w2 split (gates only stage2; overlaps stage1) ----------------
__global__ __launch_bounds__(256) void splitw2_kernel(const float* __restrict__ w2,
                                                      const float* __restrict__ sw2) {
    const size_t M1 = (size_t)DMODEL * HID;
    const size_t EW = (size_t)NEXP * M1;
    size_t off = ((size_t)blockIdx.x * blockDim.x + threadIdx.x) * 16;
    if (off < EW)  { split16(w2,  g_w2_hi,      g_w2_lo,      off); return; }
    off -= EW;
    if (off < M1)  { split16(sw2, g_w2_hi + EW, g_w2_lo + EW, off); return; }
}

// ---------------- router ----------------
__global__ __launch_bounds__(128) void router_kernel(const float* __restrict__ x,
                                                     const float* __restrict__ wr) {
    int tok = blockIdx.x;
    int tid = threadIdx.x;
    const float* xr = x + (size_t)tok * DMODEL;

    float acc[NEXP];
#pragma unroll
    for (int e = 0; e < NEXP; e++) acc[e] = 0.0f;
    for (int d = tid; d < DMODEL; d += 128) {
        float xv = xr[d];
        const float4* w4 = (const float4*)(wr + (size_t)d * NEXP);
        float4 w0 = w4[0];
        float4 w1 = w4[1];
        acc[0] += xv * w0.x; acc[1] += xv * w0.y;
        acc[2] += xv * w0.z; acc[3] += xv * w0.w;
        acc[4] += xv * w1.x; acc[5] += xv * w1.y;
        acc[6] += xv * w1.z; acc[7] += xv * w1.w;
    }
#pragma unroll
    for (int off = 16; off > 0; off >>= 1)
#pragma unroll
        for (int e = 0; e < NEXP; e++)
            acc[e] += __shfl_down_sync(0xffffffffu, acc[e], off);

    __shared__ float s[4][NEXP];
    int w = tid >> 5, l = tid & 31;
    if (l == 0)
#pragma unroll
        for (int e = 0; e < NEXP; e++) s[w][e] = acc[e];
    __syncthreads();

    if (tid == 0) {
        float lg[NEXP];
#pragma unroll
        for (int e = 0; e < NEXP; e++)
            lg[e] = s[0][e] + s[1][e] + s[2][e] + s[3][e];
        float mx = lg[0];
#pragma unroll
        for (int e = 1; e < NEXP; e++) mx = fmaxf(mx, lg[e]);
        float p[NEXP], se = 0.0f;
#pragma unroll
        for (int e = 0; e < NEXP; e++) { p[e] = expf(lg[e] - mx); se += p[e]; }
        float inv = 1.0f / se;
#pragma unroll
        for (int e = 0; e < NEXP; e++) p[e] *= inv;
        float lse = mx + logf(se);

        int b0 = 0;
#pragma unroll
        for (int e = 1; e < NEXP; e++) if (lg[e] > lg[b0]) b0 = e;
        int b1 = (b0 == 0) ? 1 : 0;
#pragma unroll
        for (int e = 0; e < NEXP; e++)
            if (e != b0 && lg[e] > lg[b1]) b1 = e;

        g_expert_idx[tok * 2 + 0] = b0;
        g_expert_idx[tok * 2 + 1] = b1;
        g_gate_w[tok * 2 + 0] = p[b0];
        g_gate_w[tok * 2 + 1] = p[b1];
        atomicAdd(&g_counts[b0], 1);
        atomicAdd(&g_counts[b1], 1);
#pragma unroll
        for (int e = 0; e < NEXP; e++) g_probs[(size_t)tok * NEXP + e] = p[e];
        g_lse2[tok] = lse * lse;
    }
}

// ---------------- post-router: reductions + plan + scatter, ONE launch ----------------
__global__ __launch_bounds__(1024) void postroute_kernel() {
    int b = blockIdx.x;
    int tid = threadIdx.x;
    __shared__ float red[1024];
    __shared__ int sfill[NEXP];

    if (b < NEXP) {
        float s = 0.0f;
        for (int i = tid; i < N_TOK; i += 1024) s += g_probs[(size_t)i * NEXP + b];
        red[tid] = s;
        __syncthreads();
        for (int st = 512; st > 0; st >>= 1) {
            if (tid < st) red[tid] += red[tid + st];
            __syncthreads();
        }
        if (tid == 0) g_probs_sum[b] = red[0];
    } else if (b == NEXP) {
        float s = 0.0f;
        for (int i = tid; i < N_TOK; i += 1024) s += g_lse2[i];
        red[tid] = s;
        __syncthreads();
        for (int st = 512; st > 0; st >>= 1) {
            if (tid < st) red[tid] += red[tid + st];
            __syncthreads();
        }
        if (tid == 0) g_zsum = red[0];
    } else {
        if (tid == 0) {
            int acc = 0;
            for (int e = 0; e <= NEXP; e++) {
                int c = (e < NEXP) ? g_counts[e] : N_TOK;
                g_seg_start[e] = acc;
                int nmb = (c + BM - 1) / BM;
                int b0 = acc / BM;
                for (int i = 0; i < nmb; i++) g_mb_expert[b0 + i] = e;
                acc += nmb * BM;
            }
            g_n_mblocks = acc / BM;
        }
        if (tid < NEXP) sfill[tid] = 0;
        __syncthreads();
        for (int tok = tid; tok < N_TOK; tok += 1024) {
#pragma unroll
            for (int k = 0; k < TOPK; k++) {
                int e = g_expert_idx[tok * 2 + k];
                int p = g_seg_start[e] + atomicAdd(&sfill[e], 1);
                g_row_tok[p] = tok;
                g_row_w[p] = g_gate_w[tok * 2 + k] * ((float)TOPK / (float)(TOPK + 1));
                g_row_pos[tok * 2 + k] = p;
            }
            int ps = g_seg_start[NEXP] + tok;
            g_row_tok[ps] = tok;
            g_row_w[ps] = 1.0f / (float)(TOPK + 1);
        }
    }
}

// ---------------- stage 1: h = silu(X@W1) * (X@W3)  [2-stage cp.async, 2 CTAs/SM] ----------------
__global__ __launch_bounds__(256, 2) void stage1_kernel() {
    int mb = blockIdx.x;
    if (mb >= g_n_mblocks) return;
    int e = g_mb_expert[mb];
    const __nv_bfloat16* W1h = g_w1_hi + (size_t)e * DMODEL * HID;
    const __nv_bfloat16* W1l = g_w1_lo + (size_t)e * DMODEL * HID;
    const __nv_bfloat16* W3h = g_w3_hi + (size_t)e * DMODEL * HID;
    const __nv_bfloat16* W3l = g_w3_lo + (size_t)e * DMODEL * HID;
    int row0 = mb * BM;
    int n0 = blockIdx.y * BN;

    extern __shared__ char dsm[];
    int* toks = (int*)dsm;
    char* base = dsm + 512;

    int tid = threadIdx.x, lane = tid & 31, warp = tid >> 5;
    if (tid < BM) toks[tid] = g_row_tok[row0 + tid];
    __syncthreads();

    int wm = warp >> 1, wn = warp & 1;

    float accg[2][4][4], accu[2][4][4];
#pragma unroll
    for (int mi = 0; mi < 2; mi++)
#pragma unroll
        for (int ni = 0; ni < 4; ni++)
#pragma unroll
            for (int q = 0; q < 4; q++) { accg[mi][ni][q] = 0.0f; accu[mi][ni][q] = 0.0f; }

    int ar = tid >> 2, ac = (tid & 3) * 8;
    int br = tid >> 3, bc = (tid & 7) * 8;
    int tok0 = toks[ar];
    int tok1 = toks[64 + ar];
    int sz0 = (tok0 >= 0) ? 16 : 0;
    int sz1 = (tok1 >= 0) ? 16 : 0;
    size_t xb0 = (tok0 >= 0) ? ((size_t)tok0 * DMODEL + ac) : 0;
    size_t xb1 = (tok1 >= 0) ? ((size_t)tok1 * DMODEL + ac) : 0;

    const int NIT = DMODEL / BK;

    auto issue = [&](int it, int buf) {
        char* st = base + buf * S1_STAGE;
        __nv_bfloat16* sAh = (__nv_bfloat16*)st;
        __nv_bfloat16* sAl = sAh + BM * ASTR;
        __nv_bfloat16* sB  = sAl + BM * ASTR;
        int kk = it * BK;
        cpa16(smaddr(&sAh[ar * ASTR + ac]),        &g_x_hi[xb0 + kk], sz0);
        cpa16(smaddr(&sAl[ar * ASTR + ac]),        &g_x_lo[xb0 + kk], sz0);
        cpa16(smaddr(&sAh[(64 + ar) * ASTR + ac]), &g_x_hi[xb1 + kk], sz1);
        cpa16(smaddr(&sAl[(64 + ar) * ASTR + ac]), &g_x_lo[xb1 + kk], sz1);
        size_t bo = (size_t)(kk + br) * HID + n0 + bc;
        cpa16(smaddr(&sB[(0 * BK + br) * BSTR + bc]), &W1h[bo], 16);
        cpa16(smaddr(&sB[(1 * BK + br) * BSTR + bc]), &W1l[bo], 16);
        cpa16(smaddr(&sB[(2 * BK + br) * BSTR + bc]), &W3h[bo], 16);
        cpa16(smaddr(&sB[(3 * BK + br) * BSTR + bc]), &W3l[bo], 16);
        cpa_commit();
    };

    issue(0, 0);

    for (int it = 0; it < NIT; it++) {
        int buf = it & 1;
        cpa_wait<0>();
        __syncthreads();
        if (it + 1 < NIT) issue(it + 1, buf ^ 1);   // overlaps with compute below

        char* st = base + buf * S1_STAGE;
        __nv_bfloat16* sAh = (__nv_bfloat16*)st;
        __nv_bfloat16* sAl = sAh + BM * ASTR;
        __nv_bfloat16* sB  = sAl + BM * ASTR;

#pragma unroll
        for (int ks = 0; ks < 2; ks++) {
            int k0 = ks * 16;
            uint32_t ah[2][4], al[2][4];
#pragma unroll
            for (int mi = 0; mi < 2; mi++) {
                int arow = wm * 32 + mi * 16 + (lane & 15);
                int acol = k0 + (lane >> 4) * 8;
                ldsm4(ah[mi][0], ah[mi][1], ah[mi][2], ah[mi][3], smaddr(&sAh[arow * ASTR + acol]));
                ldsm4(al[mi][0], al[mi][1], al[mi][2], al[mi][3], smaddr(&sAl[arow * ASTR + acol]));
            }
            int brow = k0 + (lane & 15);
            int bcolb = wn * 32 + (lane >> 4) * 8;
            // W1 pair -> accg
            {
                uint32_t bh[8], bl[8];
#pragma unroll
                for (int hh = 0; hh < 2; hh++) {
                    int bcol = bcolb + hh * 16;
                    ldsm4t(bh[hh * 4 + 0], bh[hh * 4 + 1], bh[hh * 4 + 2], bh[hh * 4 + 3],
                           smaddr(&sB[(0 * BK + brow) * BSTR + bcol]));
                    ldsm4t(bl[hh * 4 + 0], bl[hh * 4 + 1], bl[hh * 4 + 2], bl[hh * 4 + 3],
                           smaddr(&sB[(1 * BK + brow) * BSTR + bcol]));
                }
#pragma unroll
                for (int mi = 0; mi < 2; mi++)
#pragma unroll
                    for (int ni = 0; ni < 4; ni++) {
                        int rb = (ni >> 1) * 4 + (ni & 1) * 2;
                        mma16816(accg[mi][ni], ah[mi], bh[rb], bh[rb + 1]);
                        mma16816(accg[mi][ni], ah[mi], bl[rb], bl[rb + 1]);
                        mma16816(accg[mi][ni], al[mi], bh[rb], bh[rb + 1]);
                    }
            }
            // W3 pair -> accu
            {
                uint32_t bh[8], bl[8];
#pragma unroll
                for (int hh = 0; hh < 2; hh++) {
                    int bcol = bcolb + hh * 16;
                    ldsm4t(bh[hh * 4 + 0], bh[hh * 4 + 1], bh[hh * 4 + 2], bh[hh * 4 + 3],
                           smaddr(&sB[(2 * BK + brow) * BSTR + bcol]));
                    ldsm4t(bl[hh * 4 + 0], bl[hh * 4 + 1], bl[hh * 4 + 2], bl[hh * 4 + 3],
                           smaddr(&sB[(3 * BK + brow) * BSTR + bcol]));
                }
#pragma unroll
                for (int mi = 0; mi < 2; mi++)
#pragma unroll
                    for (int ni = 0; ni < 4; ni++) {
                        int rb = (ni >> 1) * 4 + (ni & 1) * 2;
                        mma16816(accu[mi][ni], ah[mi], bh[rb], bh[rb + 1]);
                        mma16816(accu[mi][ni], ah[mi], bl[rb], bl[rb + 1]);
                        mma16816(accu[mi][ni], al[mi], bh[rb], bh[rb + 1]);
                    }
            }
        }
    }

    // epilogue: SwiGLU + split to bf16 hi/lo
#pragma unroll
    for (int mi = 0; mi < 2; mi++)
#pragma unroll
        for (int ni = 0; ni < 4; ni++) {
            int r = row0 + wm * 32 + mi * 16 + (lane >> 2);
            int c = n0 + wn * 32 + ni * 8 + (lane & 3) * 2;
#pragma unroll
            for (int pr = 0; pr < 2; pr++) {
                int rr = r + pr * 8;
                float g0 = accg[mi][ni][pr * 2 + 0];
                float g1 = accg[mi][ni][pr * 2 + 1];
                float u0 = accu[mi][ni][pr * 2 + 0];
                float u1 = accu[mi][ni][pr * 2 + 1];
                float h0 = g0 / (1.0f + expf(-g0)) * u0;
                float h1 = g1 / (1.0f + expf(-g1)) * u1;
                __nv_bfloat16 h0h = __float2bfloat16(h0);
                __nv_bfloat16 h1h = __float2bfloat16(h1);
                __nv_bfloat16 h0l = __float2bfloat16(h0 - __bfloat162float(h0h));
                __nv_bfloat16 h1l = __float2bfloat16(h1 - __bfloat162float(h1h));
                *(__nv_bfloat162*)&g_h_hi[(size_t)rr * HID + c] = __nv_bfloat162(h0h, h1h);
                *(__nv_bfloat162*)&g_h_lo[(size_t)rr * HID + c] = __nv_bfloat162(h0l, h1l);
            }
        }
}

// ---------------- stage 2: ro = h @ W2  [3-stage cp.async, 2 CTAs/SM, late-issue] ----------------
__global__ __launch_bounds__(256, 2) void stage2_kernel() {
    int mb = blockIdx.x;
    if (mb >= g_n_mblocks) return;
    int e = g_mb_expert[mb];
    const __nv_bfloat16* W2h = g_w2_hi + (size_t)e * HID * DMODEL;
    const __nv_bfloat16* W2l = g_w2_lo + (size_t)e * HID * DMODEL;
    int row0 = mb * BM;
    int n0 = blockIdx.y * BN;

    extern __shared__ char dsm[];
    char* base = dsm;

    int tid = threadIdx.x, lane = tid & 31, warp = tid >> 5;
    int wm = warp >> 1, wn = warp & 1;

    float acc[2][4][4];
#pragma unroll
    for (int mi = 0; mi < 2; mi++)
#pragma unroll
        for (int ni = 0; ni < 4; ni++)
#pragma unroll
            for (int q = 0; q < 4; q++) acc[mi][ni][q] = 0.0f;

    int ar = tid >> 2, ac = (tid & 3) * 8;
    int br = tid >> 3, bc = (tid & 7) * 8;

    const int NIT = HID / BK;

    auto issue = [&](int it, int buf) {
        char* st = base + buf * S2_STAGE;
        __nv_bfloat16* sAh = (__nv_bfloat16*)st;
        __nv_bfloat16* sAl = sAh + BM * ASTR;
        __nv_bfloat16* sB  = sAl + BM * ASTR;
        int kk = it * BK;
#pragma unroll
        for (int hh = 0; hh < 2; hh++) {
            int r = hh * 64 + ar;
            size_t ao = (size_t)(row0 + r) * HID + kk + ac;
            cpa16(smaddr(&sAh[r * ASTR + ac]), &g_h_hi[ao], 16);
            cpa16(smaddr(&sAl[r * ASTR + ac]), &g_h_lo[ao], 16);
        }
        size_t bo = (size_t)(kk + br) * DMODEL + n0 + bc;
        cpa16(smaddr(&sB[(0 * BK + br) * BSTR + bc]), &W2h[bo], 16);
        cpa16(smaddr(&sB[(1 * BK + br) * BSTR + bc]), &W2l[bo], 16);
        cpa_commit();
    };

    issue(0, 0);
    issue(1, 1);

    for (int it = 0; it < NIT; it++) {
        int buf = it % 3;
        cpa_wait<1>();
        __syncthreads();

        char* st = base + buf * S2_STAGE;
        __nv_bfloat16* sAh = (__nv_bfloat16*)st;
        __nv_bfloat16* sAl = sAh + BM * ASTR;
        __nv_bfloat16* sB  = sAl + BM * ASTR;

#pragma unroll
        for (int ks = 0; ks < 2; ks++) {
            int k0 = ks * 16;
            uint32_t ah[2][4], al[2][4];
#pragma unroll
            for (int mi = 0; mi < 2; mi++) {
                int arow = wm * 32 + mi * 16 + (lane & 15);
                int acol = k0 + (lane >> 4) * 8;
                ldsm4(ah[mi][0], ah[mi][1], ah[mi][2], ah[mi][3], smaddr(&sAh[arow * ASTR + acol]));
                ldsm4(al[mi][0], al[mi][1], al[mi][2], al[mi][3], smaddr(&sAl[arow * ASTR + acol]));
            }
            uint32_t bf[2][8];
#pragma unroll
            for (int v = 0; v < 2; v++)
#pragma unroll
                for (int hh = 0; hh < 2; hh++) {
                    int brow = k0 + (lane & 15);
                    int bcol = wn * 32 + hh * 16 + (lane >> 4) * 8;
                    ldsm4t(bf[v][hh * 4 + 0], bf[v][hh * 4 + 1], bf[v][hh * 4 + 2], bf[v][hh * 4 + 3],
                           smaddr(&sB[(v * BK + brow) * BSTR + bcol]));
                }
#pragma unroll
            for (int mi = 0; mi < 2; mi++)
#pragma unroll
                for (int ni = 0; ni < 4; ni++) {
                    int rb = (ni >> 1) * 4 + (ni & 1) * 2;
                    mma16816(acc[mi][ni], ah[mi], bf[0][rb], bf[0][rb + 1]);
                    mma16816(acc[mi][ni], ah[mi], bf[1][rb], bf[1][rb + 1]);
                    mma16816(acc[mi][ni], al[mi], bf[0][rb], bf[0][rb + 1]);
                }
        }

        if (it + 2 < NIT) issue(it + 2, (it + 2) % 3);
        else cpa_commit();
    }

#pragma unroll
    for (int mi = 0; mi < 2; mi++)
#pragma unroll
        for (int ni = 0; ni < 4; ni++) {
            int r = row0 + wm * 32 + mi * 16 + (lane >> 2);
            int c = n0 + wn * 32 + ni * 8 + (lane & 3) * 2;
#pragma unroll
            for (int pr = 0; pr < 2; pr++) {
                int rr = r + pr * 8;
                float2 o = make_float2(acc[mi][ni][pr * 2 + 0], acc[mi][ni][pr * 2 + 1]);
                *(float2*)&g_ro[(size_t)rr * DMODEL + c] = o;
            }
        }
}

// ---------------- combine + losses ----------------
__global__ __launch_bounds__(256) void combine_kernel(float* __restrict__ out) {
    int tok = blockIdx.x;
    int p0 = g_row_pos[tok * 2 + 0];
    int p1 = g_row_pos[tok * 2 + 1];
    int ps = g_seg_start[NEXP] + tok;
    float w0 = g_row_w[p0];
    float w1 = g_row_w[p1];
    const float ws = 1.0f / (float)(TOPK + 1);
    for (int d = threadIdx.x; d < DMODEL; d += 256) {
        float v = w0 * g_ro[(size_t)p0 * DMODEL + d]
                + w1 * g_ro[(size_t)p1 * DMODEL + d]
                + ws * g_ro[(size_t)ps * DMODEL + d];
        out[(size_t)tok * DMODEL + d] = v;
    }
    if (tok == 0 && threadIdx.x == 0) {
        float lb = 0.0f;
        for (int e = 0; e < NEXP; e++)
            lb += (float)g_counts[e] * g_probs_sum[e];
        lb *= (float)NEXP * 0.01f / (16.0f * (float)N_TOK * (float)TOPK);
        out[(size_t)N_TOK * DMODEL + 0] = lb;
        out[(size_t)N_TOK * DMODEL + 1] = 0.001f * g_zsum / (float)N_TOK;
    }
}

// ---------------- launch ----------------
extern "C" void kernel_launch(void* const* d_in, const int* in_sizes, int n_in,
                              void* d_out, int out_size) {
    const float* x   = (const float*)d_in[0];
    const float* wr  = (const float*)d_in[1];
    const float* w1  = (const float*)d_in[2];
    const float* w3  = (const float*)d_in[3];
    const float* w2  = (const float*)d_in[4];
    const float* sw1 = (const float*)d_in[5];
    const float* sw3 = (const float*)d_in[6];
    const float* sw2 = (const float*)d_in[7];
    float* out = (float*)d_out;

    static cudaStream_t s_side = nullptr;
    static cudaEvent_t s_fork = nullptr, s_j13 = nullptr, s_j2 = nullptr;
    static int s_init_done = 0;
    if (!s_init_done) {
        cudaFuncSetAttribute(stage1_kernel, cudaFuncAttributeMaxDynamicSharedMemorySize, S1_TOTAL);
        cudaFuncSetAttribute(stage2_kernel, cudaFuncAttributeMaxDynamicSharedMemorySize, S2_TOTAL);
        cudaStreamCreateWithFlags(&s_side, cudaStreamNonBlocking);
        cudaEventCreateWithFlags(&s_fork, cudaEventDisableTiming);
        cudaEventCreateWithFlags(&s_j13, cudaEventDisableTiming);
        cudaEventCreateWithFlags(&s_j2, cudaEventDisableTiming);
        s_init_done = 1;
    }

    const size_t W13 = 18ull * 1024 * 1024;     // w1+sw1+w3+sw3 elems
    const size_t W2E = 9ull * 1024 * 1024;      // w2+sw2 elems
    const int NX = N_TOK * DMODEL;              // 4M

    // fork side stream: w1/w3 split (gates stage1), then w2 split (gates stage2,
    // overlaps stage1's HMMA-bound execution on the main stream)
    cudaEventRecord(s_fork, 0);
    cudaStreamWaitEvent(s_side, s_fork, 0);
    splitw13_kernel<<<(int)((W13 / 16 + 255) / 256), 256, 0, s_side>>>(w1, w3, sw1, sw3);
    cudaEventRecord(s_j13, s_side);
    splitw2_kernel<<<(int)((W2E / 16 + 255) / 256), 256, 0, s_side>>>(w2, sw2);
    cudaEventRecord(s_j2, s_side);

    // main stream: token-side prep
    prep_kernel<<<(NX / 16 + 255) / 256, 256>>>(x);
    router_kernel<<<N_TOK, 128>>>(x, wr);
    postroute_kernel<<<NEXP + 2, 1024>>>();

    cudaStreamWaitEvent(0, s_j13, 0);
    stage1_kernel<<<dim3(MAX_MBLOCKS, HID / BN), 256, S1_TOTAL>>>();
    cudaStreamWaitEvent(0, s_j2, 0);
    stage2_kernel<<<dim3(MAX_MBLOCKS, DMODEL / BN), 256, S2_TOTAL>>>();
    combine_kernel<<<N_TOK, 256>>>(out);
}

// round 16
// speedup vs baseline: 1.1555x; 1.1555x over previous
#include <cuda_runtime.h>
#include <cuda_bf16.h>
#include <cuda_fp16.h>
#include <math.h>
#include <stdint.h>

// ---------------- problem constants ----------------
#define N_TOK   4096
#define DMODEL  1024
#define NEXP    8
#define HID     1024
#define TOPK    2

#define BM 128
#define BN 64
#define BK 32
#define APAD 8
#define BPAD 8
#define ASTR (BK + APAD)
#define BSTR (BN + BPAD)

#define MAX_MBLOCKS 104
#define MAX_ROWS    (MAX_MBLOCKS * BM)   // 13312

// stage1: 2-stage, 2 CTAs/SM
#define S1_AH_B   (BM * ASTR * 2)                 // 10240
#define S1_B_B    (4 * BK * BSTR * 2)             // 18432
#define S1_STAGE  (2 * S1_AH_B + S1_B_B)          // 38912
#define S1_TOTAL  (512 + 2 * S1_STAGE)            // 78336

// stage2: A fp16 single + B fp16 hi/lo; 3-stage, 2 CTAs/SM
#define S2_A_B    (BM * ASTR * 2)                 // 10240
#define S2_B_B    (2 * BK * BSTR * 2)             // 9216
#define S2_STAGE  (S2_A_B + S2_B_B)               // 19456
#define S2_TOTAL  (3 * S2_STAGE)                  // 58368

// ---------------- device scratch ----------------
__device__ int   g_counts[NEXP];
__device__ float g_probs[N_TOK * NEXP];
__device__ float g_lse2[N_TOK];
__device__ float g_probs_sum[NEXP];
__device__ float g_zsum;
__device__ int   g_expert_idx[N_TOK * TOPK];
__device__ float g_gate_w[N_TOK * TOPK];
__device__ int   g_row_tok[MAX_ROWS];
__device__ float g_row_w[MAX_ROWS];
__device__ int   g_row_pos[N_TOK * TOPK];
__device__ int   g_seg_start[NEXP + 1];
__device__ int   g_mb_expert[MAX_MBLOCKS];
__device__ int   g_n_mblocks;

__device__ __nv_bfloat16 g_x_hi[(size_t)N_TOK * DMODEL];
__device__ __nv_bfloat16 g_x_lo[(size_t)N_TOK * DMODEL];
__device__ __nv_bfloat16 g_w1_hi[(size_t)(NEXP + 1) * DMODEL * HID];
__device__ __nv_bfloat16 g_w1_lo[(size_t)(NEXP + 1) * DMODEL * HID];
__device__ __nv_bfloat16 g_w3_hi[(size_t)(NEXP + 1) * DMODEL * HID];
__device__ __nv_bfloat16 g_w3_lo[(size_t)(NEXP + 1) * DMODEL * HID];
__device__ __half        g_w2_hi[(size_t)(NEXP + 1) * HID * DMODEL];
__device__ __half        g_w2_lo[(size_t)(NEXP + 1) * HID * DMODEL];
__device__ __half        g_h[(size_t)MAX_ROWS * HID];
__device__ float         g_ro[(size_t)MAX_ROWS * DMODEL];

// ---------------- asm helpers ----------------
__device__ __forceinline__ uint32_t smaddr(const void* p) {
    return (uint32_t)__cvta_generic_to_shared(p);
}
__device__ __forceinline__ void cpa16(uint32_t dst, const void* src, int szbytes) {
    asm volatile("cp.async.cg.shared.global [%0],[%1],16,%2;"
                 :: "r"(dst), "l"(src), "r"(szbytes));
}
__device__ __forceinline__ void cpa_commit() { asm volatile("cp.async.commit_group;"); }
template <int N>
__device__ __forceinline__ void cpa_wait() { asm volatile("cp.async.wait_group %0;" :: "n"(N)); }
__device__ __forceinline__ void ldsm4(uint32_t& r0, uint32_t& r1, uint32_t& r2, uint32_t& r3, uint32_t a) {
    asm volatile("ldmatrix.sync.aligned.m8n8.x4.shared.b16 {%0,%1,%2,%3},[%4];"
                 : "=r"(r0), "=r"(r1), "=r"(r2), "=r"(r3) : "r"(a));
}
__device__ __forceinline__ void ldsm4t(uint32_t& r0, uint32_t& r1, uint32_t& r2, uint32_t& r3, uint32_t a) {
    asm volatile("ldmatrix.sync.aligned.m8n8.x4.trans.shared.b16 {%0,%1,%2,%3},[%4];"
                 : "=r"(r0), "=r"(r1), "=r"(r2), "=r"(r3) : "r"(a));
}
__device__ __forceinline__ void mma16816(float* c, const uint32_t* a, uint32_t b0, uint32_t b1) {
    asm volatile("mma.sync.aligned.m16n8k16.row.col.f32.bf16.bf16.f32 "
                 "{%0,%1,%2,%3},{%4,%5,%6,%7},{%8,%9},{%0,%1,%2,%3};"
                 : "+f"(c[0]), "+f"(c[1]), "+f"(c[2]), "+f"(c[3])
                 : "r"(a[0]), "r"(a[1]), "r"(a[2]), "r"(a[3]), "r"(b0), "r"(b1));
}
__device__ __forceinline__ void mma16816h(float* c, const uint32_t* a, uint32_t b0, uint32_t b1) {
    asm volatile("mma.sync.aligned.m16n8k16.row.col.f32.f16.f16.f32 "
                 "{%0,%1,%2,%3},{%4,%5,%6,%7},{%8,%9},{%0,%1,%2,%3};"
                 : "+f"(c[0]), "+f"(c[1]), "+f"(c[2]), "+f"(c[3])
                 : "r"(a[0]), "r"(a[1]), "r"(a[2]), "r"(a[3]), "r"(b0), "r"(b1));
}

// ---------------- splits ----------------
__device__ __forceinline__ void split8v(const float4 a, const float4 b,
                                        __nv_bfloat16* __restrict__ hi,
                                        __nv_bfloat16* __restrict__ lo, size_t off) {
    float f[8] = { a.x, a.y, a.z, a.w, b.x, b.y, b.z, b.w };
    uint32_t ph[4], pl[4];
#pragma unroll
    for (int i = 0; i < 4; i++) {
        __nv_bfloat16 h0 = __float2bfloat16(f[2 * i]);
        __nv_bfloat16 h1 = __float2bfloat16(f[2 * i + 1]);
        __nv_bfloat162 hv(h0, h1);
        ph[i] = *(uint32_t*)&hv;
        __nv_bfloat162 lv(__float2bfloat16(f[2 * i] - __bfloat162float(h0)),
                          __float2bfloat16(f[2 * i + 1] - __bfloat162float(h1)));
        pl[i] = *(uint32_t*)&lv;
    }
    *(uint4*)(hi + off) = make_uint4(ph[0], ph[1], ph[2], ph[3]);
    *(uint4*)(lo + off) = make_uint4(pl[0], pl[1], pl[2], pl[3]);
}
__device__ __forceinline__ void split16(const float* __restrict__ src,
                                        __nv_bfloat16* __restrict__ hi,
                                        __nv_bfloat16* __restrict__ lo, size_t off) {
    float4 v0 = *(const float4*)(src + off);
    float4 v1 = *(const float4*)(src + off + 4);
    float4 v2 = *(const float4*)(src + off + 8);
    float4 v3 = *(const float4*)(src + off + 12);
    split8v(v0, v1, hi, lo, off);
    split8v(v2, v3, hi, lo, off + 8);
}
__device__ __forceinline__ void split8vh(const float4 a, const float4 b,
                                         __half* __restrict__ hi,
                                         __half* __restrict__ lo, size_t off) {
    float f[8] = { a.x, a.y, a.z, a.w, b.x, b.y, b.z, b.w };
    uint32_t ph[4], pl[4];
#pragma unroll
    for (int i = 0; i < 4; i++) {
        __half h0 = __float2half_rn(f[2 * i]);
        __half h1 = __float2half_rn(f[2 * i + 1]);
        __half2 hv(h0, h1);
        ph[i] = *(uint32_t*)&hv;
        __half2 lv(__float2half_rn(f[2 * i] - __half2float(h0)),
                   __float2half_rn(f[2 * i + 1] - __half2float(h1)));
        pl[i] = *(uint32_t*)&lv;
    }
    *(uint4*)(hi + off) = make_uint4(ph[0], ph[1], ph[2], ph[3]);
    *(uint4*)(lo + off) = make_uint4(pl[0], pl[1], pl[2], pl[3]);
}
__device__ __forceinline__ void split16h(const float* __restrict__ src,
                                         __half* __restrict__ hi,
                                         __half* __restrict__ lo, size_t off) {
    float4 v0 = *(const float4*)(src + off);
    float4 v1 = *(const float4*)(src + off + 4);
    float4 v2 = *(const float4*)(src + off + 8);
    float4 v3 = *(const float4*)(src + off + 12);
    split8vh(v0, v1, hi, lo, off);
    split8vh(v2, v3, hi, lo, off + 8);
}

// ---------------- prep: x split + init ----------------
__global__ __launch_bounds__(256) void prep_kernel(const float* __restrict__ x) {
    int gid = blockIdx.x * blockDim.x + threadIdx.x;
    size_t off = (size_t)gid * 16;
    if (off < (size_t)N_TOK * DMODEL) split16(x, g_x_hi, g_x_lo, off);
    if (gid < MAX_ROWS) g_row_tok[gid] = -1;
    if (gid < NEXP) g_counts[gid] = 0;
    if (gid == 0) g_zsum = 0.0f;
}

// ---------------- all weight splits, one launch ----------------
// regions (1M units): w1[0,8) sw1[8,9) w3[9,17) sw3[17,18) bf16; w2[18,26) sw2[26,27) fp16
__global__ __launch_bounds__(256) void splitw_kernel(const float* __restrict__ w1,
                                                     const float* __restrict__ w3,
                                                     const float* __restrict__ w2,
                                                     const float* __restrict__ sw1,
                                                     const float* __restrict__ sw3,
                                                     const float* __restrict__ sw2) {
    const size_t M1 = (size_t)DMODEL * HID;
    const size_t EW = (size_t)NEXP * M1;
    size_t off = ((size_t)blockIdx.x * blockDim.x + threadIdx.x) * 16;
    if (off < EW)  { split16(w1,  g_w1_hi,      g_w1_lo,      off); return; }
    off -= EW;
    if (off < M1)  { split16(sw1, g_w1_hi + EW, g_w1_lo + EW, off); return; }
    off -= M1;
    if (off < EW)  { split16(w3,  g_w3_hi,      g_w3_lo,      off); return; }
    off -= EW;
    if (off < M1)  { split16(sw3, g_w3_hi + EW, g_w3_lo + EW, off); return; }
    off -= M1;
    if (off < EW)  { split16h(w2,  g_w2_hi,      g_w2_lo,      off); return; }
    off -= EW;
    if (off < M1)  { split16h(sw2, g_w2_hi + EW, g_w2_lo + EW, off); return; }
}

// ---------------- router ----------------
__global__ __launch_bounds__(128) void router_kernel(const float* __restrict__ x,
                                                     const float* __restrict__ wr) {
    int tok = blockIdx.x;
    int tid = threadIdx.x;
    const float* xr = x + (size_t)tok * DMODEL;

    float acc[NEXP];
#pragma unroll
    for (int e = 0; e < NEXP; e++) acc[e] = 0.0f;
    for (int d = tid; d < DMODEL; d += 128) {
        float xv = xr[d];
        const float4* w4 = (const float4*)(wr + (size_t)d * NEXP);
        float4 w0 = w4[0];
        float4 w1 = w4[1];
        acc[0] += xv * w0.x; acc[1] += xv * w0.y;
        acc[2] += xv * w0.z; acc[3] += xv * w0.w;
        acc[4] += xv * w1.x; acc[5] += xv * w1.y;
        acc[6] += xv * w1.z; acc[7] += xv * w1.w;
    }
#pragma unroll
    for (int off = 16; off > 0; off >>= 1)
#pragma unroll
        for (int e = 0; e < NEXP; e++)
            acc[e] += __shfl_down_sync(0xffffffffu, acc[e], off);

    __shared__ float s[4][NEXP];
    int w = tid >> 5, l = tid & 31;
    if (l == 0)
#pragma unroll
        for (int e = 0; e < NEXP; e++) s[w][e] = acc[e];
    __syncthreads();

    if (tid == 0) {
        float lg[NEXP];
#pragma unroll
        for (int e = 0; e < NEXP; e++)
            lg[e] = s[0][e] + s[1][e] + s[2][e] + s[3][e];
        float mx = lg[0];
#pragma unroll
        for (int e = 1; e < NEXP; e++) mx = fmaxf(mx, lg[e]);
        float p[NEXP], se = 0.0f;
#pragma unroll
        for (int e = 0; e < NEXP; e++) { p[e] = expf(lg[e] - mx); se += p[e]; }
        float inv = 1.0f / se;
#pragma unroll
        for (int e = 0; e < NEXP; e++) p[e] *= inv;
        float lse = mx + logf(se);

        int b0 = 0;
#pragma unroll
        for (int e = 1; e < NEXP; e++) if (lg[e] > lg[b0]) b0 = e;
        int b1 = (b0 == 0) ? 1 : 0;
#pragma unroll
        for (int e = 0; e < NEXP; e++)
            if (e != b0 && lg[e] > lg[b1]) b1 = e;

        g_expert_idx[tok * 2 + 0] = b0;
        g_expert_idx[tok * 2 + 1] = b1;
        g_gate_w[tok * 2 + 0] = p[b0];
        g_gate_w[tok * 2 + 1] = p[b1];
        atomicAdd(&g_counts[b0], 1);
        atomicAdd(&g_counts[b1], 1);
#pragma unroll
        for (int e = 0; e < NEXP; e++) g_probs[(size_t)tok * NEXP + e] = p[e];
        g_lse2[tok] = lse * lse;
    }
}

// ---------------- post-router: reductions + plan + scatter ----------------
__global__ __launch_bounds__(1024) void postroute_kernel() {
    int b = blockIdx.x;
    int tid = threadIdx.x;
    __shared__ float red[1024];
    __shared__ int sfill[NEXP];

    if (b < NEXP) {
        float s = 0.0f;
        for (int i = tid; i < N_TOK; i += 1024) s += g_probs[(size_t)i * NEXP + b];
        red[tid] = s;
        __syncthreads();
        for (int st = 512; st > 0; st >>= 1) {
            if (tid < st) red[tid] += red[tid + st];
            __syncthreads();
        }
        if (tid == 0) g_probs_sum[b] = red[0];
    } else if (b == NEXP) {
        float s = 0.0f;
        for (int i = tid; i < N_TOK; i += 1024) s += g_lse2[i];
        red[tid] = s;
        __syncthreads();
        for (int st = 512; st > 0; st >>= 1) {
            if (tid < st) red[tid] += red[tid + st];
            __syncthreads();
        }
        if (tid == 0) g_zsum = red[0];
    } else {
        if (tid == 0) {
            int acc = 0;
            for (int e = 0; e <= NEXP; e++) {
                int c = (e < NEXP) ? g_counts[e] : N_TOK;
                g_seg_start[e] = acc;
                int nmb = (c + BM - 1) / BM;
                int b0 = acc / BM;
                for (int i = 0; i < nmb; i++) g_mb_expert[b0 + i] = e;
                acc += nmb * BM;
            }
            g_n_mblocks = acc / BM;
        }
        if (tid < NEXP) sfill[tid] = 0;
        __syncthreads();
        for (int tok = tid; tok < N_TOK; tok += 1024) {
#pragma unroll
            for (int k = 0; k < TOPK; k++) {
                int e = g_expert_idx[tok * 2 + k];
                int p = g_seg_start[e] + atomicAdd(&sfill[e], 1);
                g_row_tok[p] = tok;
                g_row_w[p] = g_gate_w[tok * 2 + k] * ((float)TOPK / (float)(TOPK + 1));
                g_row_pos[tok * 2 + k] = p;
            }
            int ps = g_seg_start[NEXP] + tok;
            g_row_tok[ps] = tok;
            g_row_w[ps] = 1.0f / (float)(TOPK + 1);
        }
    }
}

// ---------------- stage 1: h = silu(X@W1) * (X@W3)  [bf16x3, 2-stage, 2 CTAs/SM] ----------------
__global__ __launch_bounds__(256, 2) void stage1_kernel() {
    int mb = blockIdx.x;
    if (mb >= g_n_mblocks) return;
    int e = g_mb_expert[mb];
    const __nv_bfloat16* W1h = g_w1_hi + (size_t)e * DMODEL * HID;
    const __nv_bfloat16* W1l = g_w1_lo + (size_t)e * DMODEL * HID;
    const __nv_bfloat16* W3h = g_w3_hi + (size_t)e * DMODEL * HID;
    const __nv_bfloat16* W3l = g_w3_lo + (size_t)e * DMODEL * HID;
    int row0 = mb * BM;
    int n0 = blockIdx.y * BN;

    extern __shared__ char dsm[];
    int* toks = (int*)dsm;
    char* base = dsm + 512;

    int tid = threadIdx.x, lane = tid & 31, warp = tid >> 5;
    if (tid < BM) toks[tid] = g_row_tok[row0 + tid];
    __syncthreads();

    int wm = warp >> 1, wn = warp & 1;

    float accg[2][4][4], accu[2][4][4];
#pragma unroll
    for (int mi = 0; mi < 2; mi++)
#pragma unroll
        for (int ni = 0; ni < 4; ni++)
#pragma unroll
            for (int q = 0; q < 4; q++) { accg[mi][ni][q] = 0.0f; accu[mi][ni][q] = 0.0f; }

    int ar = tid >> 2, ac = (tid & 3) * 8;
    int br = tid >> 3, bc = (tid & 7) * 8;
    int tok0 = toks[ar];
    int tok1 = toks[64 + ar];
    int sz0 = (tok0 >= 0) ? 16 : 0;
    int sz1 = (tok1 >= 0) ? 16 : 0;
    size_t xb0 = (tok0 >= 0) ? ((size_t)tok0 * DMODEL + ac) : 0;
    size_t xb1 = (tok1 >= 0) ? ((size_t)tok1 * DMODEL + ac) : 0;

    const int NIT = DMODEL / BK;

    auto issue = [&](int it, int buf) {
        char* st = base + buf * S1_STAGE;
        __nv_bfloat16* sAh = (__nv_bfloat16*)st;
        __nv_bfloat16* sAl = sAh + BM * ASTR;
        __nv_bfloat16* sB  = sAl + BM * ASTR;
        int kk = it * BK;
        cpa16(smaddr(&sAh[ar * ASTR + ac]),        &g_x_hi[xb0 + kk], sz0);
        cpa16(smaddr(&sAl[ar * ASTR + ac]),        &g_x_lo[xb0 + kk], sz0);
        cpa16(smaddr(&sAh[(64 + ar) * ASTR + ac]), &g_x_hi[xb1 + kk], sz1);
        cpa16(smaddr(&sAl[(64 + ar) * ASTR + ac]), &g_x_lo[xb1 + kk], sz1);
        size_t bo = (size_t)(kk + br) * HID + n0 + bc;
        cpa16(smaddr(&sB[(0 * BK + br) * BSTR + bc]), &W1h[bo], 16);
        cpa16(smaddr(&sB[(1 * BK + br) * BSTR + bc]), &W1l[bo], 16);
        cpa16(smaddr(&sB[(2 * BK + br) * BSTR + bc]), &W3h[bo], 16);
        cpa16(smaddr(&sB[(3 * BK + br) * BSTR + bc]), &W3l[bo], 16);
        cpa_commit();
    };

    issue(0, 0);

    for (int it = 0; it < NIT; it++) {
        int buf = it & 1;
        cpa_wait<0>();
        __syncthreads();
        if (it + 1 < NIT) issue(it + 1, buf ^ 1);

        char* st = base + buf * S1_STAGE;
        __nv_bfloat16* sAh = (__nv_bfloat16*)st;
        __nv_bfloat16* sAl = sAh + BM * ASTR;
        __nv_bfloat16* sB  = sAl + BM * ASTR;

#pragma unroll
        for (int ks = 0; ks < 2; ks++) {
            int k0 = ks * 16;
            uint32_t ah[2][4], al[2][4];
#pragma unroll
            for (int mi = 0; mi < 2; mi++) {
                int arow = wm * 32 + mi * 16 + (lane & 15);
                int acol = k0 + (lane >> 4) * 8;
                ldsm4(ah[mi][0], ah[mi][1], ah[mi][2], ah[mi][3], smaddr(&sAh[arow * ASTR + acol]));
                ldsm4(al[mi][0], al[mi][1], al[mi][2], al[mi][3], smaddr(&sAl[arow * ASTR + acol]));
            }
            int brow = k0 + (lane & 15);
            int bcolb = wn * 32 + (lane >> 4) * 8;
            {
                uint32_t bh[8], bl[8];
#pragma unroll
                for (int hh = 0; hh < 2; hh++) {
                    int bcol = bcolb + hh * 16;
                    ldsm4t(bh[hh * 4 + 0], bh[hh * 4 + 1], bh[hh * 4 + 2], bh[hh * 4 + 3],
                           smaddr(&sB[(0 * BK + brow) * BSTR + bcol]));
                    ldsm4t(bl[hh * 4 + 0], bl[hh * 4 + 1], bl[hh * 4 + 2], bl[hh * 4 + 3],
                           smaddr(&sB[(1 * BK + brow) * BSTR + bcol]));
                }
#pragma unroll
                for (int mi = 0; mi < 2; mi++)
#pragma unroll
                    for (int ni = 0; ni < 4; ni++) {
                        int rb = (ni >> 1) * 4 + (ni & 1) * 2;
                        mma16816(accg[mi][ni], ah[mi], bh[rb], bh[rb + 1]);
                        mma16816(accg[mi][ni], ah[mi], bl[rb], bl[rb + 1]);
                        mma16816(accg[mi][ni], al[mi], bh[rb], bh[rb + 1]);
                    }
            }
            {
                uint32_t bh[8], bl[8];
#pragma unroll
                for (int hh = 0; hh < 2; hh++) {
                    int bcol = bcolb + hh * 16;
                    ldsm4t(bh[hh * 4 + 0], bh[hh * 4 + 1], bh[hh * 4 + 2], bh[hh * 4 + 3],
                           smaddr(&sB[(2 * BK + brow) * BSTR + bcol]));
                    ldsm4t(bl[hh * 4 + 0], bl[hh * 4 + 1], bl[hh * 4 + 2], bl[hh * 4 + 3],
                           smaddr(&sB[(3 * BK + brow) * BSTR + bcol]));
                }
#pragma unroll
                for (int mi = 0; mi < 2; mi++)
#pragma unroll
                    for (int ni = 0; ni < 4; ni++) {
                        int rb = (ni >> 1) * 4 + (ni & 1) * 2;
                        mma16816(accu[mi][ni], ah[mi], bh[rb], bh[rb + 1]);
                        mma16816(accu[mi][ni], ah[mi], bl[rb], bl[rb + 1]);
                        mma16816(accu[mi][ni], al[mi], bh[rb], bh[rb + 1]);
                    }
            }
        }
    }

    // epilogue: SwiGLU -> fp16 h
#pragma unroll
    for (int mi = 0; mi < 2; mi++)
#pragma unroll
        for (int ni = 0; ni < 4; ni++) {
            int r = row0 + wm * 32 + mi * 16 + (lane >> 2);
            int c = n0 + wn * 32 + ni * 8 + (lane & 3) * 2;
#pragma unroll
            for (int pr = 0; pr < 2; pr++) {
                int rr = r + pr * 8;
                float g0 = accg[mi][ni][pr * 2 + 0];
                float g1 = accg[mi][ni][pr * 2 + 1];
                float u0 = accu[mi][ni][pr * 2 + 0];
                float u1 = accu[mi][ni][pr * 2 + 1];
                float h0 = g0 / (1.0f + expf(-g0)) * u0;
                float h1 = g1 / (1.0f + expf(-g1)) * u1;
                *(__half2*)&g_h[(size_t)rr * HID + c] = __floats2half2_rn(h0, h1);
            }
        }
}

// ---------------- stage 2: ro = h(fp16) @ (W2hi+W2lo)  [fp16x2, 3-stage, 2 CTAs/SM] ----------------
__global__ __launch_bounds__(256, 2) void stage2_kernel() {
    int mb = blockIdx.x;
    if (mb >= g_n_mblocks) return;
    int e = g_mb_expert[mb];
    const __half* W2h = g_w2_hi + (size_t)e * HID * DMODEL;
    const __half* W2l = g_w2_lo + (size_t)e * HID * DMODEL;
    int row0 = mb * BM;
    int n0 = blockIdx.y * BN;

    extern __shared__ char dsm[];
    char* base = dsm;

    int tid = threadIdx.x, lane = tid & 31, warp = tid >> 5;
    int wm = warp >> 1, wn = warp & 1;

    float acc[2][4][4];
#pragma unroll
    for (int mi = 0; mi < 2; mi++)
#pragma unroll
        for (int ni = 0; ni < 4; ni++)
#pragma unroll
            for (int q = 0; q < 4; q++) acc[mi][ni][q] = 0.0f;

    int ar = tid >> 2, ac = (tid & 3) * 8;
    int br = tid >> 3, bc = (tid & 7) * 8;

    const int NIT = HID / BK;

    auto issue = [&](int it, int buf) {
        char* st = base + buf * S2_STAGE;
        __half* sA = (__half*)st;
        __half* sB = sA + BM * ASTR;
        int kk = it * BK;
#pragma unroll
        for (int hh = 0; hh < 2; hh++) {
            int r = hh * 64 + ar;
            cpa16(smaddr(&sA[r * ASTR + ac]), &g_h[(size_t)(row0 + r) * HID + kk + ac], 16);
        }
        size_t bo = (size_t)(kk + br) * DMODEL + n0 + bc;
        cpa16(smaddr(&sB[(0 * BK + br) * BSTR + bc]), &W2h[bo], 16);
        cpa16(smaddr(&sB[(1 * BK + br) * BSTR + bc]), &W2l[bo], 16);
        cpa_commit();
    };

    issue(0, 0);
    issue(1, 1);

    for (int it = 0; it < NIT; it++) {
        int buf = it % 3;
        cpa_wait<1>();
        __syncthreads();

        char* st = base + buf * S2_STAGE;
        __half* sA = (__half*)st;
        __half* sB = sA + BM * ASTR;

#pragma unroll
        for (int ks = 0; ks < 2; ks++) {
            int k0 = ks * 16;
            uint32_t ah[2][4];
#pragma unroll
            for (int mi = 0; mi < 2; mi++) {
                int arow = wm * 32 + mi * 16 + (lane & 15);
                int acol = k0 + (lane >> 4) * 8;
                ldsm4(ah[mi][0], ah[mi][1], ah[mi][2], ah[mi][3], smaddr(&sA[arow * ASTR + acol]));
            }
            uint32_t bf[2][8];
#pragma unroll
            for (int v = 0; v < 2; v++)
#pragma unroll
                for (int hh = 0; hh < 2; hh++) {
                    int brow = k0 + (lane & 15);
                    int bcol = wn * 32 + hh * 16 + (lane >> 4) * 8;
                    ldsm4t(bf[v][hh * 4 + 0], bf[v][hh * 4 + 1], bf[v][hh * 4 + 2], bf[v][hh * 4 + 3],
                           smaddr(&sB[(v * BK + brow) * BSTR + bcol]));
                }
#pragma unroll
            for (int mi = 0; mi < 2; mi++)
#pragma unroll
                for (int ni = 0; ni < 4; ni++) {
                    int rb = (ni >> 1) * 4 + (ni & 1) * 2;
                    mma16816h(acc[mi][ni], ah[mi], bf[0][rb], bf[0][rb + 1]);
                    mma16816h(acc[mi][ni], ah[mi], bf[1][rb], bf[1][rb + 1]);
                }
        }

        if (it + 2 < NIT) issue(it + 2, (it + 2) % 3);
        else cpa_commit();
    }

#pragma unroll
    for (int mi = 0; mi < 2; mi++)
#pragma unroll
        for (int ni = 0; ni < 4; ni++) {
            int r = row0 + wm * 32 + mi * 16 + (lane >> 2);
            int c = n0 + wn * 32 + ni * 8 + (lane & 3) * 2;
#pragma unroll
            for (int pr = 0; pr < 2; pr++) {
                int rr = r + pr * 8;
                float2 o = make_float2(acc[mi][ni][pr * 2 + 0], acc[mi][ni][pr * 2 + 1]);
                *(float2*)&g_ro[(size_t)rr * DMODEL + c] = o;
            }
        }
}

// ---------------- combine + losses ----------------
__global__ __launch_bounds__(256) void combine_kernel(float* __restrict__ out) {
    int tok = blockIdx.x;
    int p0 = g_row_pos[tok * 2 + 0];
    int p1 = g_row_pos[tok * 2 + 1];
    int ps = g_seg_start[NEXP] + tok;
    float w0 = g_row_w[p0];
    float w1 = g_row_w[p1];
    const float ws = 1.0f / (float)(TOPK + 1);
    for (int d = threadIdx.x; d < DMODEL; d += 256) {
        float v = w0 * g_ro[(size_t)p0 * DMODEL + d]
                + w1 * g_ro[(size_t)p1 * DMODEL + d]
                + ws * g_ro[(size_t)ps * DMODEL + d];
        out[(size_t)tok * DMODEL + d] = v;
    }
    if (tok == 0 && threadIdx.x == 0) {
        float lb = 0.0f;
        for (int e = 0; e < NEXP; e++)
            lb += (float)g_counts[e] * g_probs_sum[e];
        lb *= (float)NEXP * 0.01f / (16.0f * (float)N_TOK * (float)TOPK);
        out[(size_t)N_TOK * DMODEL + 0] = lb;
        out[(size_t)N_TOK * DMODEL + 1] = 0.001f * g_zsum / (float)N_TOK;
    }
}

// ---------------- launch ----------------
extern "C" void kernel_launch(void* const* d_in, const int* in_sizes, int n_in,
                              void* d_out, int out_size) {
    const float* x   = (const float*)d_in[0];
    const float* wr  = (const float*)d_in[1];
    const float* w1  = (const float*)d_in[2];
    const float* w3  = (const float*)d_in[3];
    const float* w2  = (const float*)d_in[4];
    const float* sw1 = (const float*)d_in[5];
    const float* sw3 = (const float*)d_in[6];
    const float* sw2 = (const float*)d_in[7];
    float* out = (float*)d_out;

    static int s_init_done = 0;
    if (!s_init_done) {
        cudaFuncSetAttribute(stage1_kernel, cudaFuncAttributeMaxDynamicSharedMemorySize, S1_TOTAL);
        cudaFuncSetAttribute(stage2_kernel, cudaFuncAttributeMaxDynamicSharedMemorySize, S2_TOTAL);
        s_init_done = 1;
    }

    const size_t WTOT = 27ull * 1024 * 1024;
    const int NX = N_TOK * DMODEL;

    prep_kernel<<<(NX / 16 + 255) / 256, 256>>>(x);
    splitw_kernel<<<(int)((WTOT / 16 + 255) / 256), 256>>>(w1, w3, w2, sw1, sw3, sw2);
    router_kernel<<<N_TOK, 128>>>(x, wr);
    postroute_kernel<<<NEXP + 2, 1024>>>();
    stage1_kernel<<<dim3(MAX_MBLOCKS, HID / BN), 256, S1_TOTAL>>>();
    stage2_kernel<<<dim3(MAX_MBLOCKS, DMODEL / BN), 256, S2_TOTAL>>>();
    combine_kernel<<<N_TOK, 256>>>(out);
}

// round 17
// speedup vs baseline: 1.4556x; 1.2597x over previous
#include <cuda_runtime.h>
#include <cuda_bf16.h>
#include <cuda_fp16.h>
#include <math.h>
#include <stdint.h>

// ---------------- problem constants ----------------
#define N_TOK   4096
#define DMODEL  1024
#define NEXP    8
#define HID     1024
#define TOPK    2

#define BM 128
#define BN 64
#define BK 32
#define APAD 8
#define BPAD 8
#define ASTR (BK + APAD)
#define BSTR (BN + BPAD)

#define MAX_MBLOCKS 104
#define MAX_ROWS    (MAX_MBLOCKS * BM)   // 13312

// stage1: A fp16 single + 4 B tiles (W1h,W1l,W3h,W3l) fp16; 2-stage, 2 CTAs/SM
#define S1_A_B    (BM * ASTR * 2)                 // 10240
#define S1_B_B    (4 * BK * BSTR * 2)             // 18432
#define S1_STAGE  (S1_A_B + S1_B_B)               // 28672
#define S1_TOTAL  (512 + 2 * S1_STAGE)            // 57856

// stage2: A fp16 single + B fp16 hi/lo; 3-stage, 2 CTAs/SM
#define S2_A_B    (BM * ASTR * 2)                 // 10240
#define S2_B_B    (2 * BK * BSTR * 2)             // 9216
#define S2_STAGE  (S2_A_B + S2_B_B)               // 19456
#define S2_TOTAL  (3 * S2_STAGE)                  // 58368

// ---------------- device scratch ----------------
__device__ int   g_counts[NEXP];
__device__ float g_probs[N_TOK * NEXP];
__device__ float g_lse2[N_TOK];
__device__ float g_probs_sum[NEXP];
__device__ float g_zsum;
__device__ int   g_expert_idx[N_TOK * TOPK];
__device__ float g_gate_w[N_TOK * TOPK];
__device__ int   g_row_tok[MAX_ROWS];
__device__ float g_row_w[MAX_ROWS];
__device__ int   g_row_pos[N_TOK * TOPK];
__device__ int   g_seg_start[NEXP + 1];
__device__ int   g_mb_expert[MAX_MBLOCKS];
__device__ int   g_n_mblocks;

__device__ __half g_x[(size_t)N_TOK * DMODEL];
__device__ __half g_w1_hi[(size_t)(NEXP + 1) * DMODEL * HID];
__device__ __half g_w1_lo[(size_t)(NEXP + 1) * DMODEL * HID];
__device__ __half g_w3_hi[(size_t)(NEXP + 1) * DMODEL * HID];
__device__ __half g_w3_lo[(size_t)(NEXP + 1) * DMODEL * HID];
__device__ __half g_w2_hi[(size_t)(NEXP + 1) * HID * DMODEL];
__device__ __half g_w2_lo[(size_t)(NEXP + 1) * HID * DMODEL];
__device__ __half g_h[(size_t)MAX_ROWS * HID];
__device__ float  g_ro[(size_t)MAX_ROWS * DMODEL];

// ---------------- asm helpers ----------------
__device__ __forceinline__ uint32_t smaddr(const void* p) {
    return (uint32_t)__cvta_generic_to_shared(p);
}
__device__ __forceinline__ void cpa16(uint32_t dst, const void* src, int szbytes) {
    asm volatile("cp.async.cg.shared.global [%0],[%1],16,%2;"
                 :: "r"(dst), "l"(src), "r"(szbytes));
}
__device__ __forceinline__ void cpa_commit() { asm volatile("cp.async.commit_group;"); }
template <int N>
__device__ __forceinline__ void cpa_wait() { asm volatile("cp.async.wait_group %0;" :: "n"(N)); }
__device__ __forceinline__ void ldsm4(uint32_t& r0, uint32_t& r1, uint32_t& r2, uint32_t& r3, uint32_t a) {
    asm volatile("ldmatrix.sync.aligned.m8n8.x4.shared.b16 {%0,%1,%2,%3},[%4];"
                 : "=r"(r0), "=r"(r1), "=r"(r2), "=r"(r3) : "r"(a));
}
__device__ __forceinline__ void ldsm4t(uint32_t& r0, uint32_t& r1, uint32_t& r2, uint32_t& r3, uint32_t a) {
    asm volatile("ldmatrix.sync.aligned.m8n8.x4.trans.shared.b16 {%0,%1,%2,%3},[%4];"
                 : "=r"(r0), "=r"(r1), "=r"(r2), "=r"(r3) : "r"(a));
}
__device__ __forceinline__ void mma16816h(float* c, const uint32_t* a, uint32_t b0, uint32_t b1) {
    asm volatile("mma.sync.aligned.m16n8k16.row.col.f32.f16.f16.f32 "
                 "{%0,%1,%2,%3},{%4,%5,%6,%7},{%8,%9},{%0,%1,%2,%3};"
                 : "+f"(c[0]), "+f"(c[1]), "+f"(c[2]), "+f"(c[3])
                 : "r"(a[0]), "r"(a[1]), "r"(a[2]), "r"(a[3]), "r"(b0), "r"(b1));
}

// ---------------- conversions / splits ----------------
__device__ __forceinline__ void cvt16h(const float* __restrict__ src,
                                       __half* __restrict__ dst, size_t off) {
    float4 v0 = *(const float4*)(src + off);
    float4 v1 = *(const float4*)(src + off + 4);
    float4 v2 = *(const float4*)(src + off + 8);
    float4 v3 = *(const float4*)(src + off + 12);
    float f[16] = { v0.x, v0.y, v0.z, v0.w, v1.x, v1.y, v1.z, v1.w,
                    v2.x, v2.y, v2.z, v2.w, v3.x, v3.y, v3.z, v3.w };
    uint32_t p[8];
#pragma unroll
    for (int i = 0; i < 8; i++) {
        __half2 h = __floats2half2_rn(f[2 * i], f[2 * i + 1]);
        p[i] = *(uint32_t*)&h;
    }
    *(uint4*)(dst + off)     = make_uint4(p[0], p[1], p[2], p[3]);
    *(uint4*)(dst + off + 8) = make_uint4(p[4], p[5], p[6], p[7]);
}
__device__ __forceinline__ void split8vh(const float4 a, const float4 b,
                                         __half* __restrict__ hi,
                                         __half* __restrict__ lo, size_t off) {
    float f[8] = { a.x, a.y, a.z, a.w, b.x, b.y, b.z, b.w };
    uint32_t ph[4], pl[4];
#pragma unroll
    for (int i = 0; i < 4; i++) {
        __half h0 = __float2half_rn(f[2 * i]);
        __half h1 = __float2half_rn(f[2 * i + 1]);
        __half2 hv(h0, h1);
        ph[i] = *(uint32_t*)&hv;
        __half2 lv(__float2half_rn(f[2 * i] - __half2float(h0)),
                   __float2half_rn(f[2 * i + 1] - __half2float(h1)));
        pl[i] = *(uint32_t*)&lv;
    }
    *(uint4*)(hi + off) = make_uint4(ph[0], ph[1], ph[2], ph[3]);
    *(uint4*)(lo + off) = make_uint4(pl[0], pl[1], pl[2], pl[3]);
}
__device__ __forceinline__ void split16h(const float* __restrict__ src,
                                         __half* __restrict__ hi,
                                         __half* __restrict__ lo, size_t off) {
    float4 v0 = *(const float4*)(src + off);
    float4 v1 = *(const float4*)(src + off + 4);
    float4 v2 = *(const float4*)(src + off + 8);
    float4 v3 = *(const float4*)(src + off + 12);
    split8vh(v0, v1, hi, lo, off);
    split8vh(v2, v3, hi, lo, off + 8);
}

// ---------------- prep: x -> fp16 + init ----------------
__global__ __launch_bounds__(256) void prep_kernel(const float* __restrict__ x) {
    int gid = blockIdx.x * blockDim.x + threadIdx.x;
    size_t off = (size_t)gid * 16;
    if (off < (size_t)N_TOK * DMODEL) cvt16h(x, g_x, off);
    if (gid < MAX_ROWS) g_row_tok[gid] = -1;
    if (gid < NEXP) g_counts[gid] = 0;
    if (gid == 0) g_zsum = 0.0f;
}

// ---------------- all weight splits (fp16 hi/lo), one launch ----------------
// regions (1M units): w1[0,8) sw1[8,9) w3[9,17) sw3[17,18) w2[18,26) sw2[26,27)
__global__ __launch_bounds__(256) void splitw_kernel(const float* __restrict__ w1,
                                                     const float* __restrict__ w3,
                                                     const float* __restrict__ w2,
                                                     const float* __restrict__ sw1,
                                                     const float* __restrict__ sw3,
                                                     const float* __restrict__ sw2) {
    const size_t M1 = (size_t)DMODEL * HID;
    const size_t EW = (size_t)NEXP * M1;
    size_t off = ((size_t)blockIdx.x * blockDim.x + threadIdx.x) * 16;
    if (off < EW)  { split16h(w1,  g_w1_hi,      g_w1_lo,      off); return; }
    off -= EW;
    if (off < M1)  { split16h(sw1, g_w1_hi + EW, g_w1_lo + EW, off); return; }
    off -= M1;
    if (off < EW)  { split16h(w3,  g_w3_hi,      g_w3_lo,      off); return; }
    off -= EW;
    if (off < M1)  { split16h(sw3, g_w3_hi + EW, g_w3_lo + EW, off); return; }
    off -= M1;
    if (off < EW)  { split16h(w2,  g_w2_hi,      g_w2_lo,      off); return; }
    off -= EW;
    if (off < M1)  { split16h(sw2, g_w2_hi + EW, g_w2_lo + EW, off); return; }
}

// ---------------- router ----------------
__global__ __launch_bounds__(128) void router_kernel(const float* __restrict__ x,
                                                     const float* __restrict__ wr) {
    int tok = blockIdx.x;
    int tid = threadIdx.x;
    const float* xr = x + (size_t)tok * DMODEL;

    float acc[NEXP];
#pragma unroll
    for (int e = 0; e < NEXP; e++) acc[e] = 0.0f;
    for (int d = tid; d < DMODEL; d += 128) {
        float xv = xr[d];
        const float4* w4 = (const float4*)(wr + (size_t)d * NEXP);
        float4 w0 = w4[0];
        float4 w1 = w4[1];
        acc[0] += xv * w0.x; acc[1] += xv * w0.y;
        acc[2] += xv * w0.z; acc[3] += xv * w0.w;
        acc[4] += xv * w1.x; acc[5] += xv * w1.y;
        acc[6] += xv * w1.z; acc[7] += xv * w1.w;
    }
#pragma unroll
    for (int off = 16; off > 0; off >>= 1)
#pragma unroll
        for (int e = 0; e < NEXP; e++)
            acc[e] += __shfl_down_sync(0xffffffffu, acc[e], off);

    __shared__ float s[4][NEXP];
    int w = tid >> 5, l = tid & 31;
    if (l == 0)
#pragma unroll
        for (int e = 0; e < NEXP; e++) s[w][e] = acc[e];
    __syncthreads();

    if (tid == 0) {
        float lg[NEXP];
#pragma unroll
        for (int e = 0; e < NEXP; e++)
            lg[e] = s[0][e] + s[1][e] + s[2][e] + s[3][e];
        float mx = lg[0];
#pragma unroll
        for (int e = 1; e < NEXP; e++) mx = fmaxf(mx, lg[e]);
        float p[NEXP], se = 0.0f;
#pragma unroll
        for (int e = 0; e < NEXP; e++) { p[e] = expf(lg[e] - mx); se += p[e]; }
        float inv = 1.0f / se;
#pragma unroll
        for (int e = 0; e < NEXP; e++) p[e] *= inv;
        float lse = mx + logf(se);

        int b0 = 0;
#pragma unroll
        for (int e = 1; e < NEXP; e++) if (lg[e] > lg[b0]) b0 = e;
        int b1 = (b0 == 0) ? 1 : 0;
#pragma unroll
        for (int e = 0; e < NEXP; e++)
            if (e != b0 && lg[e] > lg[b1]) b1 = e;

        g_expert_idx[tok * 2 + 0] = b0;
        g_expert_idx[tok * 2 + 1] = b1;
        g_gate_w[tok * 2 + 0] = p[b0];
        g_gate_w[tok * 2 + 1] = p[b1];
        atomicAdd(&g_counts[b0], 1);
        atomicAdd(&g_counts[b1], 1);
#pragma unroll
        for (int e = 0; e < NEXP; e++) g_probs[(size_t)tok * NEXP + e] = p[e];
        g_lse2[tok] = lse * lse;
    }
}

// ---------------- post-router: reductions + plan + scatter ----------------
__global__ __launch_bounds__(1024) void postroute_kernel() {
    int b = blockIdx.x;
    int tid = threadIdx.x;
    __shared__ float red[1024];
    __shared__ int sfill[NEXP];

    if (b < NEXP) {
        float s = 0.0f;
        for (int i = tid; i < N_TOK; i += 1024) s += g_probs[(size_t)i * NEXP + b];
        red[tid] = s;
        __syncthreads();
        for (int st = 512; st > 0; st >>= 1) {
            if (tid < st) red[tid] += red[tid + st];
            __syncthreads();
        }
        if (tid == 0) g_probs_sum[b] = red[0];
    } else if (b == NEXP) {
        float s = 0.0f;
        for (int i = tid; i < N_TOK; i += 1024) s += g_lse2[i];
        red[tid] = s;
        __syncthreads();
        for (int st = 512; st > 0; st >>= 1) {
            if (tid < st) red[tid] += red[tid + st];
            __syncthreads();
        }
        if (tid == 0) g_zsum = red[0];
    } else {
        if (tid == 0) {
            int acc = 0;
            for (int e = 0; e <= NEXP; e++) {
                int c = (e < NEXP) ? g_counts[e] : N_TOK;
                g_seg_start[e] = acc;
                int nmb = (c + BM - 1) / BM;
                int b0 = acc / BM;
                for (int i = 0; i < nmb; i++) g_mb_expert[b0 + i] = e;
                acc += nmb * BM;
            }
            g_n_mblocks = acc / BM;
        }
        if (tid < NEXP) sfill[tid] = 0;
        __syncthreads();
        for (int tok = tid; tok < N_TOK; tok += 1024) {
#pragma unroll
            for (int k = 0; k < TOPK; k++) {
                int e = g_expert_idx[tok * 2 + k];
                int p = g_seg_start[e] + atomicAdd(&sfill[e], 1);
                g_row_tok[p] = tok;
                g_row_w[p] = g_gate_w[tok * 2 + k] * ((float)TOPK / (float)(TOPK + 1));
                g_row_pos[tok * 2 + k] = p;
            }
            int ps = g_seg_start[NEXP] + tok;
            g_row_tok[ps] = tok;
            g_row_w[ps] = 1.0f / (float)(TOPK + 1);
        }
    }
}

// ---------------- stage 1: h = silu(X@W1) * (X@W3)  [fp16 x, fp16x2 W; 2-stage, 2 CTAs/SM] ----------------
__global__ __launch_bounds__(256, 2) void stage1_kernel() {
    int mb = blockIdx.x;
    if (mb >= g_n_mblocks) return;
    int e = g_mb_expert[mb];
    const __half* W1h = g_w1_hi + (size_t)e * DMODEL * HID;
    const __half* W1l = g_w1_lo + (size_t)e * DMODEL * HID;
    const __half* W3h = g_w3_hi + (size_t)e * DMODEL * HID;
    const __half* W3l = g_w3_lo + (size_t)e * DMODEL * HID;
    int row0 = mb * BM;
    int n0 = blockIdx.y * BN;

    extern __shared__ char dsm[];
    int* toks = (int*)dsm;
    char* base = dsm + 512;

    int tid = threadIdx.x, lane = tid & 31, warp = tid >> 5;
    if (tid < BM) toks[tid] = g_row_tok[row0 + tid];
    __syncthreads();

    int wm = warp >> 1, wn = warp & 1;

    float accg[2][4][4], accu[2][4][4];
#pragma unroll
    for (int mi = 0; mi < 2; mi++)
#pragma unroll
        for (int ni = 0; ni < 4; ni++)
#pragma unroll
            for (int q = 0; q < 4; q++) { accg[mi][ni][q] = 0.0f; accu[mi][ni][q] = 0.0f; }

    int ar = tid >> 2, ac = (tid & 3) * 8;
    int br = tid >> 3, bc = (tid & 7) * 8;
    int tok0 = toks[ar];
    int tok1 = toks[64 + ar];
    int sz0 = (tok0 >= 0) ? 16 : 0;
    int sz1 = (tok1 >= 0) ? 16 : 0;
    size_t xb0 = (tok0 >= 0) ? ((size_t)tok0 * DMODEL + ac) : 0;
    size_t xb1 = (tok1 >= 0) ? ((size_t)tok1 * DMODEL + ac) : 0;

    const int NIT = DMODEL / BK;

    auto issue = [&](int it, int buf) {
        char* st = base + buf * S1_STAGE;
        __half* sA = (__half*)st;
        __half* sB = sA + BM * ASTR;
        int kk = it * BK;
        cpa16(smaddr(&sA[ar * ASTR + ac]),        &g_x[xb0 + kk], sz0);
        cpa16(smaddr(&sA[(64 + ar) * ASTR + ac]), &g_x[xb1 + kk], sz1);
        size_t bo = (size_t)(kk + br) * HID + n0 + bc;
        cpa16(smaddr(&sB[(0 * BK + br) * BSTR + bc]), &W1h[bo], 16);
        cpa16(smaddr(&sB[(1 * BK + br) * BSTR + bc]), &W1l[bo], 16);
        cpa16(smaddr(&sB[(2 * BK + br) * BSTR + bc]), &W3h[bo], 16);
        cpa16(smaddr(&sB[(3 * BK + br) * BSTR + bc]), &W3l[bo], 16);
        cpa_commit();
    };

    issue(0, 0);

    for (int it = 0; it < NIT; it++) {
        int buf = it & 1;
        cpa_wait<0>();
        __syncthreads();
        if (it + 1 < NIT) issue(it + 1, buf ^ 1);

        char* st = base + buf * S1_STAGE;
        __half* sA = (__half*)st;
        __half* sB = sA + BM * ASTR;

#pragma unroll
        for (int ks = 0; ks < 2; ks++) {
            int k0 = ks * 16;
            uint32_t ah[2][4];
#pragma unroll
            for (int mi = 0; mi < 2; mi++) {
                int arow = wm * 32 + mi * 16 + (lane & 15);
                int acol = k0 + (lane >> 4) * 8;
                ldsm4(ah[mi][0], ah[mi][1], ah[mi][2], ah[mi][3], smaddr(&sA[arow * ASTR + acol]));
            }
            int brow = k0 + (lane & 15);
            int bcolb = wn * 32 + (lane >> 4) * 8;
            uint32_t bf[4][8];
#pragma unroll
            for (int v = 0; v < 4; v++)
#pragma unroll
                for (int hh = 0; hh < 2; hh++) {
                    int bcol = bcolb + hh * 16;
                    ldsm4t(bf[v][hh * 4 + 0], bf[v][hh * 4 + 1], bf[v][hh * 4 + 2], bf[v][hh * 4 + 3],
                           smaddr(&sB[(v * BK + brow) * BSTR + bcol]));
                }
#pragma unroll
            for (int mi = 0; mi < 2; mi++)
#pragma unroll
                for (int ni = 0; ni < 4; ni++) {
                    int rb = (ni >> 1) * 4 + (ni & 1) * 2;
                    mma16816h(accg[mi][ni], ah[mi], bf[0][rb], bf[0][rb + 1]);
                    mma16816h(accg[mi][ni], ah[mi], bf[1][rb], bf[1][rb + 1]);
                    mma16816h(accu[mi][ni], ah[mi], bf[2][rb], bf[2][rb + 1]);
                    mma16816h(accu[mi][ni], ah[mi], bf[3][rb], bf[3][rb + 1]);
                }
        }
    }

    // epilogue: SwiGLU -> fp16 h
#pragma unroll
    for (int mi = 0; mi < 2; mi++)
#pragma unroll
        for (int ni = 0; ni < 4; ni++) {
            int r = row0 + wm * 32 + mi * 16 + (lane >> 2);
            int c = n0 + wn * 32 + ni * 8 + (lane & 3) * 2;
#pragma unroll
            for (int pr = 0; pr < 2; pr++) {
                int rr = r + pr * 8;
                float g0 = accg[mi][ni][pr * 2 + 0];
                float g1 = accg[mi][ni][pr * 2 + 1];
                float u0 = accu[mi][ni][pr * 2 + 0];
                float u1 = accu[mi][ni][pr * 2 + 1];
                float h0 = g0 / (1.0f + expf(-g0)) * u0;
                float h1 = g1 / (1.0f + expf(-g1)) * u1;
                *(__half2*)&g_h[(size_t)rr * HID + c] = __floats2half2_rn(h0, h1);
            }
        }
}

// ---------------- stage 2: ro = h(fp16) @ (W2hi+W2lo)  [fp16x2, 3-stage, 2 CTAs/SM] ----------------
__global__ __launch_bounds__(256, 2) void stage2_kernel() {
    int mb = blockIdx.x;
    if (mb >= g_n_mblocks) return;
    int e = g_mb_expert[mb];
    const __half* W2h = g_w2_hi + (size_t)e * HID * DMODEL;
    const __half* W2l = g_w2_lo + (size_t)e * HID * DMODEL;
    int row0 = mb * BM;
    int n0 = blockIdx.y * BN;

    extern __shared__ char dsm[];
    char* base = dsm;

    int tid = threadIdx.x, lane = tid & 31, warp = tid >> 5;
    int wm = warp >> 1, wn = warp & 1;

    float acc[2][4][4];
#pragma unroll
    for (int mi = 0; mi < 2; mi++)
#pragma unroll
        for (int ni = 0; ni < 4; ni++)
#pragma unroll
            for (int q = 0; q < 4; q++) acc[mi][ni][q] = 0.0f;

    int ar = tid >> 2, ac = (tid & 3) * 8;
    int br = tid >> 3, bc = (tid & 7) * 8;

    const int NIT = HID / BK;

    auto issue = [&](int it, int buf) {
        char* st = base + buf * S2_STAGE;
        __half* sA = (__half*)st;
        __half* sB = sA + BM * ASTR;
        int kk = it * BK;
#pragma unroll
        for (int hh = 0; hh < 2; hh++) {
            int r = hh * 64 + ar;
            cpa16(smaddr(&sA[r * ASTR + ac]), &g_h[(size_t)(row0 + r) * HID + kk + ac], 16);
        }
        size_t bo = (size_t)(kk + br) * DMODEL + n0 + bc;
        cpa16(smaddr(&sB[(0 * BK + br) * BSTR + bc]), &W2h[bo], 16);
        cpa16(smaddr(&sB[(1 * BK + br) * BSTR + bc]), &W2l[bo], 16);
        cpa_commit();
    };

    issue(0, 0);
    issue(1, 1);

    for (int it = 0; it < NIT; it++) {
        int buf = it % 3;
        cpa_wait<1>();
        __syncthreads();

        char* st = base + buf * S2_STAGE;
        __half* sA = (__half*)st;
        __half* sB = sA + BM * ASTR;

#pragma unroll
        for (int ks = 0; ks < 2; ks++) {
            int k0 = ks * 16;
            uint32_t ah[2][4];
#pragma unroll
            for (int mi = 0; mi < 2; mi++) {
                int arow = wm * 32 + mi * 16 + (lane & 15);
                int acol = k0 + (lane >> 4) * 8;
                ldsm4(ah[mi][0], ah[mi][1], ah[mi][2], ah[mi][3], smaddr(&sA[arow * ASTR + acol]));
            }
            uint32_t bf[2][8];
#pragma unroll
            for (int v = 0; v < 2; v++)
#pragma unroll
                for (int hh = 0; hh < 2; hh++) {
                    int brow = k0 + (lane & 15);
                    int bcol = wn * 32 + hh * 16 + (lane >> 4) * 8;
                    ldsm4t(bf[v][hh * 4 + 0], bf[v][hh * 4 + 1], bf[v][hh * 4 + 2], bf[v][hh * 4 + 3],
                           smaddr(&sB[(v * BK + brow) * BSTR + bcol]));
                }
#pragma unroll
            for (int mi = 0; mi < 2; mi++)
#pragma unroll
                for (int ni = 0; ni < 4; ni++) {
                    int rb = (ni >> 1) * 4 + (ni & 1) * 2;
                    mma16816h(acc[mi][ni], ah[mi], bf[0][rb], bf[0][rb + 1]);
                    mma16816h(acc[mi][ni], ah[mi], bf[1][rb], bf[1][rb + 1]);
                }
        }

        if (it + 2 < NIT) issue(it + 2, (it + 2) % 3);
        else cpa_commit();
    }

#pragma unroll
    for (int mi = 0; mi < 2; mi++)
#pragma unroll
        for (int ni = 0; ni < 4; ni++) {
            int r = row0 + wm * 32 + mi * 16 + (lane >> 2);
            int c = n0 + wn * 32 + ni * 8 + (lane & 3) * 2;
#pragma unroll
            for (int pr = 0; pr < 2; pr++) {
                int rr = r + pr * 8;
                float2 o = make_float2(acc[mi][ni][pr * 2 + 0], acc[mi][ni][pr * 2 + 1]);
                *(float2*)&g_ro[(size_t)rr * DMODEL + c] = o;
            }
        }
}

// ---------------- combine + losses ----------------
__global__ __launch_bounds__(256) void combine_kernel(float* __restrict__ out) {
    int tok = blockIdx.x;
    int p0 = g_row_pos[tok * 2 + 0];
    int p1 = g_row_pos[tok * 2 + 1];
    int ps = g_seg_start[NEXP] + tok;
    float w0 = g_row_w[p0];
    float w1 = g_row_w[p1];
    const float ws = 1.0f / (float)(TOPK + 1);
    for (int d = threadIdx.x; d < DMODEL; d += 256) {
        float v = w0 * g_ro[(size_t)p0 * DMODEL + d]
                + w1 * g_ro[(size_t)p1 * DMODEL + d]
                + ws * g_ro[(size_t)ps * DMODEL + d];
        out[(size_t)tok * DMODEL + d] = v;
    }
    if (tok == 0 && threadIdx.x == 0) {
        float lb = 0.0f;
        for (int e = 0; e < NEXP; e++)
            lb += (float)g_counts[e] * g_probs_sum[e];
        lb *= (float)NEXP * 0.01f / (16.0f * (float)N_TOK * (float)TOPK);
        out[(size_t)N_TOK * DMODEL + 0] = lb;
        out[(size_t)N_TOK * DMODEL + 1] = 0.001f * g_zsum / (float)N_TOK;
    }
}

// ---------------- launch ----------------
extern "C" void kernel_launch(void* const* d_in, const int* in_sizes, int n_in,
                              void* d_out, int out_size) {
    const float* x   = (const float*)d_in[0];
    const float* wr  = (const float*)d_in[1];
    const float* w1  = (const float*)d_in[2];
    const float* w3  = (const float*)d_in[3];
    const float* w2  = (const float*)d_in[4];
    const float* sw1 = (const float*)d_in[5];
    const float* sw3 = (const float*)d_in[6];
    const float* sw2 = (const float*)d_in[7];
    float* out = (float*)d_out;

    static int s_init_done = 0;
    if (!s_init_done) {
        cudaFuncSetAttribute(stage1_kernel, cudaFuncAttributeMaxDynamicSharedMemorySize, S1_TOTAL);
        cudaFuncSetAttribute(stage2_kernel, cudaFuncAttributeMaxDynamicSharedMemorySize, S2_TOTAL);
        s_init_done = 1;
    }

    const size_t WTOT = 27ull * 1024 * 1024;
    const int NX = N_TOK * DMODEL;

    prep_kernel<<<(NX / 16 + 255) / 256, 256>>>(x);
    splitw_kernel<<<(int)((WTOT / 16 + 255) / 256), 256>>>(w1, w3, w2, sw1, sw3, sw2);
    router_kernel<<<N_TOK, 128>>>(x, wr);
    postroute_kernel<<<NEXP + 2, 1024>>>();
    stage1_kernel<<<dim3(MAX_MBLOCKS, HID / BN), 256, S1_TOTAL>>>();
    stage2_kernel<<<dim3(MAX_MBLOCKS, DMODEL / BN), 256, S2_TOTAL>>>();
    combine_kernel<<<N_TOK, 256>>>(out);
}